// round 17
// baseline (speedup 1.0000x reference)
#include <cuda_runtime.h>
#include <cuda_bf16.h>
#include <cuda_fp16.h>
#include <cstdint>

#define Bz 8
#define Cc 512
#define Nn 1024

// ---------------- device scratch (no allocations allowed) --------------------
__device__ float g_yf[Bz*Cc*Nn];               // conv output [B,C,N]
__device__ float g_yn[Bz*Cc*Nn];               // layernorm output [B,C,N]
__device__ __half g_attnh[(size_t)64*1024*1024]; // attn [64 z][1024 n][1024 m] fp16
// bf16 operand buffers
__device__ __nv_bfloat16 g_xbf [Bz*Nn*Cc];     // x^T  [b,n,512]
__device__ __nv_bfloat16 g_ynbf[Bz*Nn*Cc];     // yn^T [b,n,512]
__device__ __nv_bfloat16 g_qwb [Cc*Cc];        // 0.125*q_w  [co,512]
__device__ __nv_bfloat16 g_kvwb[2*Cc*Cc];      // kv_w [co,512]
__device__ __nv_bfloat16 g_pwb [Cc*Cc];        // proj_w [co,512]
__device__ __nv_bfloat16 g_qbf [Bz*Nn*Cc];     // q  [b,n,512]
__device__ __nv_bfloat16 g_kbf [Bz*Nn*Cc];     // k  [b,n,512]
__device__ __nv_bfloat16 g_vbf [Bz*Nn*Cc];     // v  [b,n,512]
__device__ __nv_bfloat16 g_obf [Bz*Nn*Cc];     // attn out [b,n,512]
__device__ __nv_bfloat16 g_vthi[(size_t)64*64*1024];   // v^T [z,d,m]
__device__ __nv_bfloat16 g_chi [(size_t)64*1024*1024]; // coeff [z,n,m]

// =================== warp-MMA helpers (plain sm_103-safe PTX) ================
__device__ __forceinline__ uint32_t smem_u32(const void* p) {
    uint32_t a;
    asm("{ .reg .u64 t; cvta.to.shared.u64 t, %1; cvt.u32.u64 %0, t; }"
        : "=r"(a) : "l"(p));
    return a;
}
__device__ __forceinline__ void ldsm_x4(uint32_t& r0, uint32_t& r1, uint32_t& r2,
                                        uint32_t& r3, uint32_t addr) {
    asm volatile("ldmatrix.sync.aligned.m8n8.x4.shared.b16 {%0,%1,%2,%3}, [%4];"
                 : "=r"(r0), "=r"(r1), "=r"(r2), "=r"(r3) : "r"(addr));
}
__device__ __forceinline__ void ldsm_x2(uint32_t& r0, uint32_t& r1, uint32_t addr) {
    asm volatile("ldmatrix.sync.aligned.m8n8.x2.shared.b16 {%0,%1}, [%2];"
                 : "=r"(r0), "=r"(r1) : "r"(addr));
}
__device__ __forceinline__ void mma_bf16(float* c, const uint32_t* a, const uint32_t* b) {
    asm volatile("mma.sync.aligned.m16n8k16.row.col.f32.bf16.bf16.f32 "
                 "{%0,%1,%2,%3}, {%4,%5,%6,%7}, {%8,%9}, {%0,%1,%2,%3};"
                 : "+f"(c[0]), "+f"(c[1]), "+f"(c[2]), "+f"(c[3])
                 : "r"(a[0]), "r"(a[1]), "r"(a[2]), "r"(a[3]), "r"(b[0]), "r"(b[1]));
}
#define CP_ASYNC16(dst, src) \
    asm volatile("cp.async.cg.shared.global [%0], [%1], 16;" :: "r"(dst), "l"(src))
#define CP_COMMIT() asm volatile("cp.async.commit_group;" ::: "memory")
#define CP_WAIT(n)  asm volatile("cp.async.wait_group %0;" :: "n"(n) : "memory")
#define PADB 144   // padded row stride (72 bf16): conflict-free ldmatrix, 16B-mult

// ================= K1: fused conv | weight-convert | x transpose =============
#define K1_SMEM (38*40*4 + 64*4)

__device__ void conv_body(int bc, int t,
                          const float* __restrict__ y,
                          const float* __restrict__ w3, const float* __restrict__ b3,
                          const float* __restrict__ w5, const float* __restrict__ b5,
                          const float* __restrict__ w7, const float* __restrict__ b7)
{
    extern __shared__ __align__(16) char k1sm[];
    float* tile  = (float*)k1sm;            // [38][40]
    float* wsum  = tile + 38*40;            // [49]
    float* biasp = wsum + 49;

    int c = bc & (Cc-1);
    if (t < 49) {
        int dy = t / 7, dx = t % 7;
        float w = w7[c*49 + t];
        if (dy >= 1 && dy <= 5 && dx >= 1 && dx <= 5) w += w5[c*25 + (dy-1)*5 + (dx-1)];
        if (dy >= 2 && dy <= 4 && dx >= 2 && dx <= 4) w += w3[c*9  + (dy-2)*3 + (dx-2)];
        wsum[t] = w;
    }
    if (t == 64) *biasp = b3[c] + b5[c] + b7[c];

    const float* yp = y + (size_t)bc * Nn;
    for (int i = t; i < 38*38; i += 256) {
        int rr = i / 38, cc = i % 38;
        int r = rr - 3, cl = cc - 3;
        float v = 0.f;
        if (r >= 0 && r < 32 && cl >= 0 && cl < 32) v = yp[r*32 + cl];
        tile[rr*40 + cc] = v;
    }
    __syncthreads();

    int r  = t >> 3;
    int cq = (t & 7) * 4;
    float bias = *biasp;
    float a0 = bias, a1 = bias, a2 = bias, a3 = bias;
    #pragma unroll
    for (int dy = 0; dy < 7; dy++) {
        float rv[12];
        const float* rp = &tile[(r+dy)*40 + cq];
        *(float4*)&rv[0] = *(const float4*)rp;
        *(float4*)&rv[4] = *(const float4*)(rp + 4);
        *(float4*)&rv[8] = *(const float4*)(rp + 8);
        #pragma unroll
        for (int dx = 0; dx < 7; dx++) {
            float w = wsum[dy*7 + dx];
            a0 += w*rv[dx];   a1 += w*rv[dx+1];
            a2 += w*rv[dx+2]; a3 += w*rv[dx+3];
        }
    }
    *(float4*)&g_yf[(size_t)bc*Nn + r*32 + cq] = make_float4(a0, a1, a2, a3);
}

__device__ void wcvt_body(int b2, int t,
                          const float* __restrict__ q_w,
                          const float* __restrict__ kv_w,
                          const float* __restrict__ proj_w)
{
    const float* S; __nv_bfloat16* D; float scale; int off;
    if (b2 < 256)      { S = q_w;    D = g_qwb;  scale = 0.125f; off = b2; }
    else if (b2 < 768) { S = kv_w;   D = g_kvwb; scale = 1.f;    off = b2 - 256; }
    else               { S = proj_w; D = g_pwb;  scale = 1.f;    off = b2 - 768; }
    int i4 = off * 256 + t;
    float4 v = *(const float4*)&S[(size_t)i4 * 4];
    __nv_bfloat16 o[4] = {__float2bfloat16(v.x*scale), __float2bfloat16(v.y*scale),
                          __float2bfloat16(v.z*scale), __float2bfloat16(v.w*scale)};
    *(uint2*)&D[(size_t)i4 * 4] = *(uint2*)o;
}

__device__ void tcvt_body(int idx, int t, const float* __restrict__ S,
                          __nv_bfloat16* __restrict__ D)
{
    extern __shared__ __align__(16) char k1sm[];
    float* tile = (float*)k1sm;             // [32][33]
    int n0 = (idx & 31) * 32;
    int c0 = ((idx >> 5) & 15) * 32;
    int b  = idx >> 9;
    int tx = t & 31, ty = t >> 5;
    #pragma unroll
    for (int i = ty; i < 32; i += 8)
        tile[i*33 + tx] = S[((size_t)b*Cc + c0 + i)*Nn + n0 + tx];
    __syncthreads();
    #pragma unroll
    for (int i = ty; i < 32; i += 8)
        D[((size_t)b*Nn + n0 + i)*Cc + c0 + tx] = __float2bfloat16(tile[tx*33 + i]);
}

__global__ void __launch_bounds__(256)
k1_kernel(const float* __restrict__ y,
          const float* __restrict__ w3, const float* __restrict__ b3,
          const float* __restrict__ w5, const float* __restrict__ b5,
          const float* __restrict__ w7, const float* __restrict__ b7,
          const float* __restrict__ x,
          const float* __restrict__ q_w, const float* __restrict__ kv_w,
          const float* __restrict__ proj_w)
{
    int blk = blockIdx.x, t = threadIdx.x;
    if (blk < 4096)       conv_body(blk, t, y, w3, b3, w5, b5, w7, b7);
    else if (blk < 5120)  wcvt_body(blk - 4096, t, q_w, kv_w, proj_w);
    else                  tcvt_body(blk - 5120, t, x, g_xbf);
}

// ---------------- standalone yn transpose-convert ----------------------------
__global__ void tcvt_yn_kernel()
{
    extern __shared__ __align__(16) char k1sm[];
    tcvt_body(blockIdx.x, threadIdx.x, g_yn, g_ynbf);
}

// ---------------- layernorm body (dynamic smem) -------------------------------
__device__ void ln_body(int blk, int t, const float* __restrict__ lnw,
                        const float* __restrict__ lnb)
{
    extern __shared__ __align__(16) char dsm[];
    float* sh = (float*)dsm;                 // [2][8][32]

    int b    = blk >> 5;
    int n0   = (blk & 31) * 32;
    int lane = t & 31;
    int g    = t >> 5;
    int n    = n0 + lane;

    const float* base = g_yf + (size_t)b*Cc*Nn + n;
    float s = 0.f, s2 = 0.f;
    for (int c = g; c < Cc; c += 8) {
        float v = base[(size_t)c*Nn];
        s += v; s2 += v*v;
    }
    sh[(0*8 + g)*32 + lane] = s;
    sh[(1*8 + g)*32 + lane] = s2;
    __syncthreads();
    if (g == 0) {
        float a = 0.f, a2 = 0.f;
        #pragma unroll
        for (int i = 0; i < 8; i++) {
            a  += sh[(0*8 + i)*32 + lane];
            a2 += sh[(1*8 + i)*32 + lane];
        }
        float mu  = a * (1.f/512.f);
        float var = a2 * (1.f/512.f) - mu*mu;
        sh[0*32 + lane]       = mu;
        sh[(1*8)*32 + lane]   = rsqrtf(var + 1e-5f);
    }
    __syncthreads();
    float mu = sh[0*32 + lane], rs = sh[(1*8)*32 + lane];
    float* ob = g_yn + (size_t)b*Cc*Nn + n;
    for (int c = g; c < Cc; c += 8) {
        float v = base[(size_t)c*Nn];
        ob[(size_t)c*Nn] = (v - mu) * rs * lnw[c] + lnb[c];
    }
}

// ------- bf16 mma projection GEMM body, single-sync double-buffered ----------
#define GM_SMEM (4*128*PADB)
__device__ void gemm_body(int t, int co0, int n0, int b,
                          const __nv_bfloat16* __restrict__ A,
                          const __nv_bfloat16* __restrict__ W,
                          __nv_bfloat16* __restrict__ D0,
                          __nv_bfloat16* __restrict__ D1)
{
    extern __shared__ __align__(16) char sm[];
    uint32_t sb = smem_u32(sm);

    int warp = t >> 5, lane = t & 31;
    int wn = warp >> 2, wm = warp & 3;

    const char* asrc = (const char*)(A + ((size_t)(b*Nn + n0))*Cc);
    const char* wsrc = (const char*)(W + (size_t)co0*Cc);

    auto issue = [&](int kc, int bi) {
        uint32_t base = sb + bi*(2*128*PADB);
        for (int i = t; i < 1024; i += 256) {
            int row = i >> 3, cb = (i & 7) * 16;
            CP_ASYNC16(base + row*PADB + cb, asrc + (size_t)row*1024 + kc*2 + cb);
            CP_ASYNC16(base + 128*PADB + row*PADB + cb, wsrc + (size_t)row*1024 + kc*2 + cb);
        }
        CP_COMMIT();
    };
    issue(0, 0);

    float acc[4][4][4] = {};
    int lr16 = lane & 15, lh = lane >> 4;
    int l8 = lane & 7,  lq = (lane & 15) >> 3;

    for (int c8 = 0; c8 < 8; c8++) {
        CP_WAIT(0);
        __syncthreads();
        if (c8 < 7) issue((c8+1)*64, (c8+1)&1);
        uint32_t base = sb + (c8&1)*(2*128*PADB);
        uint32_t aAddr = base + (wn*64 + lr16)*PADB + lh*16;
        uint32_t bAddr = base + 128*PADB + (wm*32 + l8)*PADB + lq*16;
        #pragma unroll
        for (int k0 = 0; k0 < 64; k0 += 16) {
            uint32_t a[4][4], bb[4][2];
            #pragma unroll
            for (int mi = 0; mi < 4; mi++)
                ldsm_x4(a[mi][0], a[mi][1], a[mi][2], a[mi][3],
                        aAddr + mi*16*PADB + k0*2);
            #pragma unroll
            for (int ni = 0; ni < 4; ni++)
                ldsm_x2(bb[ni][0], bb[ni][1], bAddr + ni*8*PADB + k0*2);
            #pragma unroll
            for (int mi = 0; mi < 4; mi++)
                #pragma unroll
                for (int ni = 0; ni < 4; ni++)
                    mma_bf16(acc[mi][ni], a[mi], bb[ni]);
        }
    }

    __nv_bfloat16* D = (co0 < Cc) ? D0 : D1;
    int cadj = (co0 < Cc) ? 0 : Cc;
    int rbase = n0 + wn*64 + (lane >> 2);
    int cbase = co0 - cadj + wm*32 + (lane & 3)*2;
    #pragma unroll
    for (int mi = 0; mi < 4; mi++)
        #pragma unroll
        for (int ni = 0; ni < 4; ni++) {
            float* c = acc[mi][ni];
            size_t r0i = ((size_t)(b*Nn) + rbase + mi*16)*Cc + cbase + ni*8;
            __nv_bfloat162 p0, p1;
            p0.x = __float2bfloat16(c[0]); p0.y = __float2bfloat16(c[1]);
            p1.x = __float2bfloat16(c[2]); p1.y = __float2bfloat16(c[3]);
            *(__nv_bfloat162*)&D[r0i]        = p0;
            *(__nv_bfloat162*)&D[r0i + 8*Cc] = p1;
        }
}

// ------- fused launch: gemm-q (blocks 0..255) | layernorm (blocks 256..511) ---
__global__ void __launch_bounds__(256, 2)
lnq_kernel(const float* __restrict__ lnw, const float* __restrict__ lnb)
{
    int blk = blockIdx.x, t = threadIdx.x;
    if (blk < 256) {
        int co0 = (blk & 3) * 128;
        int n0  = ((blk >> 2) & 7) * 128;
        int b   = blk >> 5;
        gemm_body(t, co0, n0, b, g_xbf, g_qwb, g_qbf, g_qbf);
    } else {
        ln_body(blk - 256, t, lnw, lnb);
    }
}

// ------- kv gemm (standard grid) ----------------------------------------------
__global__ void __launch_bounds__(256, 2)
gemm_kv_kernel()
{
    gemm_body(threadIdx.x, blockIdx.x * 128, blockIdx.y * 128, blockIdx.z,
              g_ynbf, g_kvwb, g_kbf, g_vbf);
}

// ---------- v transpose body ---------------------------------------------------
__device__ void vt_body(int f, int t)
{
    extern __shared__ __align__(16) char dsm[];
    __nv_bfloat16* tile = (__nv_bfloat16*)dsm;   // [32][33]
    int d0 = (f & 1) * 32, m0 = ((f >> 1) & 31) * 32, z = f >> 6;
    int b = z >> 3, h = z & 7;
    int tx = t & 31, ty = t >> 5;
    #pragma unroll
    for (int i = ty; i < 32; i += 8)
        tile[i*33 + tx] = g_vbf[((size_t)(b*Nn + m0 + i))*Cc + h*64 + d0 + tx];
    __syncthreads();
    #pragma unroll
    for (int i = ty; i < 32; i += 8)
        g_vthi[((size_t)z*64 + d0 + i)*1024 + m0 + tx] = tile[tx*33 + i];
}

// ------- fused launch: QK^T (blocks 0..511) | v-transpose (512..4607) ---------
#define QK_SMEM (3*128*PADB)
__global__ void __launch_bounds__(256, 2) qkvt_kernel()
{
    int blk = blockIdx.x, t = threadIdx.x;
    if (blk >= 512) { vt_body(blk - 512, t); return; }

    extern __shared__ __align__(16) char sm[];
    uint32_t sb = smem_u32(sm);
    const uint32_t QT = 0, KT = 128*PADB;

    int warp = t >> 5, lane = t & 31;
    int n0 = (blk & 7) * 128, z = blk >> 3;
    int b = z >> 3, h = z & 7;
    int wn = warp >> 2, wm = warp & 3;

    const char* qs = (const char*)(g_qbf + ((size_t)(b*Nn + n0)*Cc + h*64));
    const char* ks = (const char*)(g_kbf + ((size_t)(b*Nn)*Cc + h*64));

    for (int i = t; i < 1024; i += 256) {
        int row = i >> 3, cb = (i & 7) * 16;
        CP_ASYNC16(sb + QT + row*PADB + cb, qs + (size_t)row*1024 + cb);
    }
    auto issueK = [&](int m0, int bi) {
        uint32_t base = sb + KT + bi*(128*PADB);
        for (int i = t; i < 1024; i += 256) {
            int row = i >> 3, cb = (i & 7) * 16;
            CP_ASYNC16(base + row*PADB + cb, ks + (size_t)(m0 + row)*1024 + cb);
        }
        CP_COMMIT();
    };
    issueK(0, 0);

    int lr16 = lane & 15, lh = lane >> 4;
    int l8 = lane & 7,  lq = (lane & 15) >> 3;

    for (int c8 = 0; c8 < 8; c8++) {
        CP_WAIT(0);
        __syncthreads();
        if (c8 < 7) issueK((c8+1)*128, (c8+1)&1);

        float acc[4][4][4] = {};
        uint32_t aAddr = sb + QT + (wn*64 + lr16)*PADB + lh*16;
        uint32_t bAddr = sb + KT + (c8&1)*(128*PADB) + (wm*32 + l8)*PADB + lq*16;
        #pragma unroll
        for (int k0 = 0; k0 < 64; k0 += 16) {
            uint32_t a[4][4], bb[4][2];
            #pragma unroll
            for (int mi = 0; mi < 4; mi++)
                ldsm_x4(a[mi][0], a[mi][1], a[mi][2], a[mi][3],
                        aAddr + mi*16*PADB + k0*2);
            #pragma unroll
            for (int ni = 0; ni < 4; ni++)
                ldsm_x2(bb[ni][0], bb[ni][1], bAddr + ni*8*PADB + k0*2);
            #pragma unroll
            for (int mi = 0; mi < 4; mi++)
                #pragma unroll
                for (int ni = 0; ni < 4; ni++)
                    mma_bf16(acc[mi][ni], a[mi], bb[ni]);
        }

        int rbase = n0 + wn*64 + (lane >> 2);
        int cbase = c8*128 + wm*32 + (lane & 3)*2;
        #pragma unroll
        for (int mi = 0; mi < 4; mi++)
            #pragma unroll
            for (int ni = 0; ni < 4; ni++) {
                float* c = acc[mi][ni];
                __half* A = g_attnh + ((size_t)z*Nn + rbase + mi*16)*Nn + cbase + ni*8;
                *(__half2*)&A[0]            = __floats2half2_rn(c[0], c[1]);
                *(__half2*)&A[(size_t)8*Nn] = __floats2half2_rn(c[2], c[3]);
            }
    }
}

// ------- kernel 6: exact top-k via fp16-domain >=-count bisection ------------
__device__ __forceinline__ __half u2h(unsigned k) {
    unsigned short b = (k & 0x8000u) ? (unsigned short)(k ^ 0x8000u)
                                     : (unsigned short)(~k & 0xFFFFu);
    return __ushort_as_half(b);
}

__global__ void select_kernel(const float* __restrict__ kr1, const float* __restrict__ kr2)
{
    int row  = blockIdx.x * 8 + (threadIdx.x >> 5);   // z*1024 + n
    int lane = threadIdx.x & 31;

    float r1 = kr1[0], r2 = kr2[0];
    int k1 = (int)(1024.f * (1.f/(1.f+expf(-r1)))); k1 = min(max(k1,1),1024);
    int k2 = (int)(1024.f * (1.f/(1.f+expf(-r2)))); k2 = min(max(k2,1),1024);

    const __half* rp = g_attnh + (size_t)row * Nn;
    __half2 kh[16];
    #pragma unroll
    for (int i = 0; i < 4; i++) {
        uint4 v = *(const uint4*)(rp + i*256 + lane*8);
        kh[i*4+0] = *(__half2*)&v.x;
        kh[i*4+1] = *(__half2*)&v.y;
        kh[i*4+2] = *(__half2*)&v.z;
        kh[i*4+3] = *(__half2*)&v.w;
    }

    __half2 mx2 = kh[0];
    #pragma unroll
    for (int i = 1; i < 16; i++) mx2 = __hmax2(mx2, kh[i]);
    float M = fmaxf(__low2float(mx2), __high2float(mx2));
    #pragma unroll
    for (int o = 16; o; o >>= 1)
        M = fmaxf(M, __shfl_xor_sync(0xffffffffu, M, o));
    __half mxh = __float2half(M);

    unsigned T1 = 0, T2 = 0;
    bool d1 = false, d2 = false;
    __half th1 = u2h(0), th2 = u2h(0);
    for (int bit = 15; bit >= 0; --bit) {
        if (d1 && d2) break;
        unsigned bm = 1u << bit;
        __half p1 = u2h(T1 | bm), p2 = u2h(T2 | bm);
        bool a1 = !d1 && __hle(p1, mxh);
        bool a2 = !d2 && __hle(p2, mxh);
        if (!a1 && !a2) continue;
        __half2 t1v = __half2half2(p1), t2v = __half2half2(p2);
        __half2 a1h = __float2half2_rn(0.f), a2h = a1h;
        #pragma unroll
        for (int i = 0; i < 16; i++) {
            a1h = __hadd2(a1h, __hge2(kh[i], t1v));
            a2h = __hadd2(a2h, __hge2(kh[i], t2v));
        }
        int c1 = (int)(__low2float(a1h) + __high2float(a1h));
        int c2 = (int)(__low2float(a2h) + __high2float(a2h));
        unsigned cc = (unsigned)c1 | ((unsigned)c2 << 16);
        cc = __reduce_add_sync(0xffffffffu, cc);
        c1 = (int)(cc & 0xffffu); c2 = (int)(cc >> 16);
        if (a1 && c1 >= k1) { T1 |= bm; th1 = p1; d1 = (c1 == k1); }
        if (a2 && c2 >= k2) { T2 |= bm; th2 = p2; d2 = (c2 == k2); }
    }
    if (!d1) th1 = u2h(T1);
    if (!d2) th2 = u2h(T2);
    if (d1) {
        float mn = 1e30f;
        #pragma unroll
        for (int i = 0; i < 16; i++) {
            __half lo = __low2half(kh[i]), hi = __high2half(kh[i]);
            if (__hge(lo, th1)) mn = fminf(mn, __half2float(lo));
            if (__hge(hi, th1)) mn = fminf(mn, __half2float(hi));
        }
        #pragma unroll
        for (int o = 16; o; o >>= 1)
            mn = fminf(mn, __shfl_xor_sync(0xffffffffu, mn, o));
        th1 = __float2half(mn);
    }
    if (d2) {
        float mn = 1e30f;
        #pragma unroll
        for (int i = 0; i < 16; i++) {
            __half lo = __low2half(kh[i]), hi = __high2half(kh[i]);
            if (__hge(lo, th2)) mn = fminf(mn, __half2float(lo));
            if (__hge(hi, th2)) mn = fminf(mn, __half2float(hi));
        }
        #pragma unroll
        for (int o = 16; o; o >>= 1)
            mn = fminf(mn, __shfl_xor_sync(0xffffffffu, mn, o));
        th2 = __float2half(mn);
    }

    // elements below both thresholds have weight 0 -> skip their exp entirely
    __half thmin = __hle(th1, th2) ? th1 : th2;
    float ev[32];
    float s1 = 0.f, s2 = 0.f;
    #pragma unroll
    for (int i = 0; i < 16; i++) {
        __half lo = __low2half(kh[i]), hi = __high2half(kh[i]);
        ev[2*i]   = __hge(lo, thmin) ? __expf(__half2float(lo) - M) : 0.f;
        ev[2*i+1] = __hge(hi, thmin) ? __expf(__half2float(hi) - M) : 0.f;
        if (__hge(lo, th1)) s1 += ev[2*i];
        if (__hge(hi, th1)) s1 += ev[2*i+1];
        if (__hge(lo, th2)) s2 += ev[2*i];
        if (__hge(hi, th2)) s2 += ev[2*i+1];
    }
    #pragma unroll
    for (int o = 16; o; o >>= 1) {
        s1 += __shfl_xor_sync(0xffffffffu, s1, o);
        s2 += __shfl_xor_sync(0xffffffffu, s2, o);
    }
    float c1f = 0.6f / s1, c2f = 0.4f / s2;
    __nv_bfloat16* ch = g_chi + (size_t)row * Nn;
    #pragma unroll
    for (int i = 0; i < 4; i++) {
        __nv_bfloat16 ob[8];
        #pragma unroll
        for (int j = 0; j < 8; j++) {
            int e = i*8 + j;
            __half h = (e & 1) ? __high2half(kh[e >> 1]) : __low2half(kh[e >> 1]);
            float w = (__hge(h, th1) ? c1f : 0.f) + (__hge(h, th2) ? c2f : 0.f);
            ob[j] = __float2bfloat16(ev[e] * w);
        }
        *(uint4*)(ch + i*256 + lane*8) = *(const uint4*)ob;
    }
}

// ------- kernel 7: AV via mma.sync bf16, single-sync double-buffered ---------
#define AV_SMEM (2*(192*PADB))
__global__ void __launch_bounds__(256, 2) av_mma_kernel()
{
    extern __shared__ __align__(16) char sm[];
    uint32_t sb = smem_u32(sm);

    int t = threadIdx.x, warp = t >> 5, lane = t & 31;
    int n0 = blockIdx.x * 128, z = blockIdx.y;
    int b = z >> 3, h = z & 7;
    int wn = warp >> 1, wd = warp & 1;

    const char* ch = (const char*)(g_chi  + ((size_t)z*Nn + n0)*Nn);
    const char* vh = (const char*)(g_vthi + (size_t)z*64*1024);

    auto issue = [&](int m0, int bi) {
        uint32_t base = sb + bi*(192*PADB);
        for (int i = t; i < 1024; i += 256) {
            int row = i >> 3, cb = (i & 7) * 16;
            CP_ASYNC16(base + row*PADB + cb, ch + (size_t)row*2048 + m0*2 + cb);
        }
        for (int i = t; i < 512; i += 256) {
            int row = i >> 3, cb = (i & 7) * 16;
            CP_ASYNC16(base + 128*PADB + row*PADB + cb, vh + (size_t)row*2048 + m0*2 + cb);
        }
        CP_COMMIT();
    };
    issue(0, 0);

    float acc[2][4][4] = {};
    int lr16 = lane & 15, lh = lane >> 4;
    int l8 = lane & 7,  lq = (lane & 15) >> 3;

    for (int c16 = 0; c16 < 16; c16++) {
        CP_WAIT(0);
        __syncthreads();
        if (c16 < 15) issue((c16+1)*64, (c16+1)&1);
        uint32_t base = sb + (c16&1)*(192*PADB);
        uint32_t aAddr = base + (wn*32 + lr16)*PADB + lh*16;
        uint32_t bAddr = base + 128*PADB + (wd*32 + l8)*PADB + lq*16;
        #pragma unroll
        for (int k0 = 0; k0 < 64; k0 += 16) {
            uint32_t a[2][4], bb[4][2];
            #pragma unroll
            for (int mi = 0; mi < 2; mi++)
                ldsm_x4(a[mi][0], a[mi][1], a[mi][2], a[mi][3],
                        aAddr + mi*16*PADB + k0*2);
            #pragma unroll
            for (int ni = 0; ni < 4; ni++)
                ldsm_x2(bb[ni][0], bb[ni][1], bAddr + ni*8*PADB + k0*2);
            #pragma unroll
            for (int mi = 0; mi < 2; mi++)
                #pragma unroll
                for (int ni = 0; ni < 4; ni++)
                    mma_bf16(acc[mi][ni], a[mi], bb[ni]);
        }
    }

    int rbase = n0 + wn*32 + (lane >> 2);
    int cbase = h*64 + wd*32 + (lane & 3)*2;
    #pragma unroll
    for (int mi = 0; mi < 2; mi++)
        #pragma unroll
        for (int ni = 0; ni < 4; ni++) {
            float* c = acc[mi][ni];
            size_t o0 = ((size_t)(b*Nn) + rbase + mi*16)*Cc + cbase + ni*8;
            __nv_bfloat162 p0, p1;
            p0.x = __float2bfloat16(c[0]); p0.y = __float2bfloat16(c[1]);
            p1.x = __float2bfloat16(c[2]); p1.y = __float2bfloat16(c[3]);
            *(__nv_bfloat162*)&g_obf[o0]        = p0;
            *(__nv_bfloat162*)&g_obf[o0 + 8*Cc] = p1;
        }
}

// ------- kernel 8: proj via mma; out[b,c,n] = W.o + bias + x ------------------
#define PJ_SMEM (4*128*PADB)
__global__ void __launch_bounds__(256, 2)
proj_mma_kernel(const float* __restrict__ bias, const float* __restrict__ x,
                float* __restrict__ OUT)
{
    extern __shared__ __align__(16) char sm[];
    uint32_t sb = smem_u32(sm);

    int t = threadIdx.x, warp = t >> 5, lane = t & 31;
    int c0 = blockIdx.x * 128, n0 = blockIdx.y * 128, b = blockIdx.z;
    int wc = warp >> 2, wnn = warp & 3;

    const char* wsrc = (const char*)(g_pwb + (size_t)c0*Cc);
    const char* osrc = (const char*)(g_obf + ((size_t)(b*Nn + n0))*Cc);

    auto issue = [&](int kc, int bi) {
        uint32_t base = sb + bi*(2*128*PADB);
        for (int i = t; i < 1024; i += 256) {
            int row = i >> 3, cb = (i & 7) * 16;
            CP_ASYNC16(base + row*PADB + cb, wsrc + (size_t)row*1024 + kc*2 + cb);
            CP_ASYNC16(base + 128*PADB + row*PADB + cb, osrc + (size_t)row*1024 + kc*2 + cb);
        }
        CP_COMMIT();
    };
    issue(0, 0);

    float acc[4][4][4] = {};
    int lr16 = lane & 15, lh = lane >> 4;
    int l8 = lane & 7,  lq = (lane & 15) >> 3;

    for (int c8 = 0; c8 < 8; c8++) {
        CP_WAIT(0);
        __syncthreads();
        if (c8 < 7) issue((c8+1)*64, (c8+1)&1);
        uint32_t base = sb + (c8&1)*(2*128*PADB);
        uint32_t aAddr = base + (wc*64 + lr16)*PADB + lh*16;
        uint32_t bAddr = base + 128*PADB + (wnn*32 + l8)*PADB + lq*16;
        #pragma unroll
        for (int k0 = 0; k0 < 64; k0 += 16) {
            uint32_t a[4][4], bb[4][2];
            #pragma unroll
            for (int mi = 0; mi < 4; mi++)
                ldsm_x4(a[mi][0], a[mi][1], a[mi][2], a[mi][3],
                        aAddr + mi*16*PADB + k0*2);
            #pragma unroll
            for (int ni = 0; ni < 4; ni++)
                ldsm_x2(bb[ni][0], bb[ni][1], bAddr + ni*8*PADB + k0*2);
            #pragma unroll
            for (int mi = 0; mi < 4; mi++)
                #pragma unroll
                for (int ni = 0; ni < 4; ni++)
                    mma_bf16(acc[mi][ni], a[mi], bb[ni]);
        }
    }

    int cb0 = c0 + wc*64 + (lane >> 2);
    int nb0 = n0 + wnn*32 + (lane & 3)*2;
    #pragma unroll
    for (int mi = 0; mi < 4; mi++) {
        int c = cb0 + mi*16;
        float bs0 = bias[c], bs8 = bias[c + 8];
        #pragma unroll
        for (int ni = 0; ni < 4; ni++) {
            float* a = acc[mi][ni];
            int n = nb0 + ni*8;
            size_t i0 = ((size_t)b*Cc + c)*Nn + n;
            float2 x0 = *(const float2*)&x[i0];
            *(float2*)&OUT[i0] = make_float2(a[0] + bs0 + x0.x, a[1] + bs0 + x0.y);
            size_t i8 = i0 + (size_t)8*Nn;
            float2 x8 = *(const float2*)&x[i8];
            *(float2*)&OUT[i8] = make_float2(a[2] + bs8 + x8.x, a[3] + bs8 + x8.y);
        }
    }
}

// -----------------------------------------------------------------------------
extern "C" void kernel_launch(void* const* d_in, const int* in_sizes, int n_in,
                              void* d_out, int out_size)
{
    const float* x       = (const float*)d_in[0];
    const float* y       = (const float*)d_in[1];
    const float* q_w     = (const float*)d_in[2];
    const float* kv_w    = (const float*)d_in[3];
    const float* proj_w  = (const float*)d_in[4];
    const float* proj_b  = (const float*)d_in[5];
    const float* conv1_w = (const float*)d_in[6];
    const float* conv1_b = (const float*)d_in[7];
    const float* conv2_w = (const float*)d_in[8];
    const float* conv2_b = (const float*)d_in[9];
    const float* conv3_w = (const float*)d_in[10];
    const float* conv3_b = (const float*)d_in[11];
    const float* ln_w    = (const float*)d_in[12];
    const float* ln_b    = (const float*)d_in[13];
    const float* kr1     = (const float*)d_in[14];
    const float* kr2     = (const float*)d_in[15];
    float* out = (float*)d_out;

    cudaFuncSetAttribute(lnq_kernel,      cudaFuncAttributeMaxDynamicSharedMemorySize, GM_SMEM);
    cudaFuncSetAttribute(gemm_kv_kernel,  cudaFuncAttributeMaxDynamicSharedMemorySize, GM_SMEM);
    cudaFuncSetAttribute(qkvt_kernel,     cudaFuncAttributeMaxDynamicSharedMemorySize, QK_SMEM);
    cudaFuncSetAttribute(av_mma_kernel,   cudaFuncAttributeMaxDynamicSharedMemorySize, AV_SMEM);
    cudaFuncSetAttribute(proj_mma_kernel, cudaFuncAttributeMaxDynamicSharedMemorySize, PJ_SMEM);

    // K1: conv | weight-cvt | x transpose-cvt (all independent)
    k1_kernel<<<4096 + 1024 + 4096, 256, K1_SMEM>>>(
        y, conv1_w, conv1_b, conv2_w, conv2_b, conv3_w, conv3_b,
        x, q_w, kv_w, proj_w);

    // gemm-q | layernorm (independent, fused launch)
    lnq_kernel<<<512, 256, GM_SMEM>>>(ln_w, ln_b);

    tcvt_yn_kernel<<<4096, 256, K1_SMEM>>>();

    gemm_kv_kernel<<<dim3(8, 8, Bz), 256, GM_SMEM>>>();

    // QK^T | v-transpose (independent, fused launch)
    qkvt_kernel<<<512 + 4096, 256, QK_SMEM>>>();

    select_kernel<<<Bz*8*Nn/8, 256>>>(kr1, kr2);
    av_mma_kernel<<<dim3(Nn/128, Bz*8), 256, AV_SMEM>>>();
    proj_mma_kernel<<<dim3(Cc/128, Nn/128, Bz), 256, PJ_SMEM>>>(proj_b, x, out);
}